// round 12
// baseline (speedup 1.0000x reference)
#include <cuda_runtime.h>
#include <cuda_fp16.h>
#include <cstdint>

#define N_CAP 100000
#define E_CAP 1600000

// ---------------- scratch (__device__ globals, zero-initialized) ----------------
__device__ float  g_dinv[2][N_CAP];
__device__ int    g_deg[2][N_CAP];        // zero at entry; scan3 re-zeroes
__device__ int    g_incl[2][N_CAP];
__device__ int    g_rowptr[2][N_CAP + 1];
__device__ int    g_bsum[2][128];
__device__ int    g_rank[2][E_CAP];       // per-edge rank within its dst row
__device__ int    g_esrc[2][E_CAP];       // dst-sorted src ids
__device__ __half g_A[2][(size_t)N_CAP * 64];   // h' = dinv * (X @ W), fp16
__device__ float  g_B[2][(size_t)N_CAP * 64];   // Z1 (fp32)

static __device__ __forceinline__ int clampi(int v, int lo, int hi) {
    return v < lo ? lo : (v > hi ? hi : v);
}

// ---------------- hist: per-edge rank claim (4 edges/thread, atomic MLP) ---------

__global__ void hist_kernel(const int* __restrict__ e0, const int* __restrict__ e1,
                            int E, int n) {
    int g = blockIdx.y;
    const int* dst = (g == 0 ? e0 : e1) + E;
    int base_e = blockIdx.x * 1024 + threadIdx.x;
#pragma unroll
    for (int k = 0; k < 4; k++) {
        int e = base_e + k * 256;
        if (e < E) {
            int d = clampi(dst[e], 0, n - 1);
            g_rank[g][e] = atomicAdd(&g_deg[g][d], 1);
        }
    }
}

// ---------------- scan1: per-1024-chunk inclusive scan + dinv ----------------

__global__ void scan1_kernel(int n) {
    __shared__ int sh[1024];
    int g = blockIdx.y;
    int i = blockIdx.x * 1024 + threadIdx.x;
    int v = (i < n) ? g_deg[g][i] : 0;
    if (i < n) g_dinv[g][i] = rsqrtf((float)v + 1.0f);  // self-loop
    sh[threadIdx.x] = v;
    __syncthreads();
#pragma unroll
    for (int off = 1; off < 1024; off <<= 1) {
        int t = (threadIdx.x >= off) ? sh[threadIdx.x - off] : 0;
        __syncthreads();
        sh[threadIdx.x] += t;
        __syncthreads();
    }
    if (i < n) g_incl[g][i] = sh[threadIdx.x];
    if (threadIdx.x == 1023) g_bsum[g][blockIdx.x] = sh[1023];
}

// ---------------- scan3: rowptr finalize + deg reset ----------------

__global__ void scan3_kernel(int n, int E) {
    __shared__ int sh_off;
    int g = blockIdx.y;
    int t = threadIdx.x;
    int chunk = (blockIdx.x * 256) >> 10;
    if (t < 32) {
        int s = 0;
        for (int k = t; k < chunk; k += 32) s += g_bsum[g][k];
#pragma unroll
        for (int o = 16; o; o >>= 1) s += __shfl_down_sync(0xFFFFFFFFu, s, o);
        if (t == 0) sh_off = s;
    }
    __syncthreads();
    int off = sh_off;
    int i = blockIdx.x * 256 + t;
    if (i < n) {
        g_rowptr[g][i] = g_incl[g][i] - g_deg[g][i] + off;  // exclusive
        g_deg[g][i] = 0;                                     // reset invariant
    }
    if (i == 0) g_rowptr[g][n] = E;
}

// ---------------- claim: atomic-free CSR scatter (4 edges/thread MLP) ------------

__global__ void claim_kernel(const int* __restrict__ e0, const int* __restrict__ e1,
                             int E, int n) {
    int g = blockIdx.y;
    const int* base = (g == 0 ? e0 : e1);
    int base_e = blockIdx.x * 1024 + threadIdx.x;
#pragma unroll
    for (int k = 0; k < 4; k++) {
        int e = base_e + k * 256;
        if (e < E) {
            int s = clampi(base[e], 0, n - 1);
            int d = clampi(base[E + e], 0, n - 1);
            int pos = g_rowptr[g][d] + g_rank[g][e];
            g_esrc[g][pos] = s;
        }
    }
}

// ---------------- GEMM: h' = dinv * ((relu?)X @ W), fp16 out (R9 version) --------

__global__ void gemm64_kernel(const float* __restrict__ X0, const float* __restrict__ X1,
                              int use_B, const float* __restrict__ W, int n, int relu_in) {
    __shared__ float Ws[64][64];
    __shared__ float Xs[64][65];
    int g = blockIdx.y;
    const float* X = use_B ? (const float*)g_B[g] : (g == 0 ? X0 : X1);
    __half* Y = g_A[g];
    int tid = threadIdx.x;
    for (int i = tid; i < 64 * 16; i += 256)
        ((float4*)Ws)[i] = ((const float4*)W)[i];
    int row0 = blockIdx.x * 64;
    for (int i = tid; i < 64 * 16; i += 256) {
        int r = i >> 4, c = (i & 15) * 4;
        float4 v = make_float4(0.f, 0.f, 0.f, 0.f);
        if (row0 + r < n) v = *(const float4*)&X[(size_t)(row0 + r) * 64 + c];
        if (relu_in) {
            v.x = fmaxf(v.x, 0.f); v.y = fmaxf(v.y, 0.f);
            v.z = fmaxf(v.z, 0.f); v.w = fmaxf(v.w, 0.f);
        }
        Xs[r][c] = v.x; Xs[r][c + 1] = v.y; Xs[r][c + 2] = v.z; Xs[r][c + 3] = v.w;
    }
    __syncthreads();
    int tr = (tid >> 4) * 4;
    int tc = tid & 15;
    float acc[4][4] = {};
#pragma unroll
    for (int k = 0; k < 64; k++) {
        float4 w4 = ((const float4*)&Ws[k][0])[tc];
        float x0 = Xs[tr + 0][k], x1 = Xs[tr + 1][k];
        float x2 = Xs[tr + 2][k], x3 = Xs[tr + 3][k];
        acc[0][0] += x0 * w4.x; acc[0][1] += x0 * w4.y; acc[0][2] += x0 * w4.z; acc[0][3] += x0 * w4.w;
        acc[1][0] += x1 * w4.x; acc[1][1] += x1 * w4.y; acc[1][2] += x1 * w4.z; acc[1][3] += x1 * w4.w;
        acc[2][0] += x2 * w4.x; acc[2][1] += x2 * w4.y; acc[2][2] += x2 * w4.z; acc[2][3] += x2 * w4.w;
        acc[3][0] += x3 * w4.x; acc[3][1] += x3 * w4.y; acc[3][2] += x3 * w4.z; acc[3][3] += x3 * w4.w;
    }
#pragma unroll
    for (int i = 0; i < 4; i++) {
        int r = row0 + tr + i;
        if (r < n) {
            float dv = g_dinv[g][r];
            __half2 p0 = __floats2half2_rn(acc[i][0] * dv, acc[i][1] * dv);
            __half2 p1 = __floats2half2_rn(acc[i][2] * dv, acc[i][3] * dv);
            uint2 u = make_uint2(*(unsigned*)&p0, *(unsigned*)&p1);
            *(uint2*)&Y[(size_t)r * 64 + tc * 4] = u;
        }
    }
}

// ---------------- aggregation: Z = dinv[d]*(Σ h'[src] + h'[d]) + b ----------------
// warp per node; lanes split into 4 groups of 8 (uint4 = 8 fp16 cols each) so ONE
// warp load covers FOUR edge rows. 4 slots -> 16 edges in flight (avg degree 16
// completes in a single iteration). shfl_xor(8) + shfl_xor(16) fold quarters.

__global__ void agg_kernel(const float* __restrict__ b, int n,
                           const float* __restrict__ Wy, const float* __restrict__ by,
                           const float* __restrict__ Wp, const float* __restrict__ bp,
                           const float* __restrict__ Wb, const float* __restrict__ bb,
                           float* __restrict__ out) {
    int g = blockIdx.y;
    int node = (blockIdx.x * blockDim.x + threadIdx.x) >> 5;
    int lane = threadIdx.x & 31;
    if (node >= n) return;
    const uint4* __restrict__ h8 = (const uint4*)g_A[g];  // 8 uint4 per row (8 cols each)
    const int*   __restrict__ ep = g_esrc[g];

    int q  = lane >> 3;   // quarter: which of 4 edges in the slot-group
    int c8 = lane & 7;    // col group: cols 8*c8 .. 8*c8+7
    float a0 = 0.f, a1 = 0.f, a2 = 0.f, a3 = 0.f;
    float a4 = 0.f, a5 = 0.f, a6 = 0.f, a7 = 0.f;

    int beg = g_rowptr[g][node];
    int end = g_rowptr[g][node + 1];

    for (int jj = beg; jj < end; jj += 16) {
#pragma unroll
        for (int s = 0; s < 4; s++) {
            int my = jj + s * 4 + q;
            if (my < end) {
                int src = ep[my];
                uint4 u = h8[(size_t)src * 8 + c8];
                float2 f0 = __half22float2(*(__half2*)&u.x);
                float2 f1 = __half22float2(*(__half2*)&u.y);
                float2 f2 = __half22float2(*(__half2*)&u.z);
                float2 f3 = __half22float2(*(__half2*)&u.w);
                a0 += f0.x; a1 += f0.y; a2 += f1.x; a3 += f1.y;
                a4 += f2.x; a5 += f2.y; a6 += f3.x; a7 += f3.y;
            }
        }
    }
    // fold quarters
#pragma unroll
    for (int o = 8; o <= 16; o <<= 1) {
        a0 += __shfl_xor_sync(0xFFFFFFFFu, a0, o);
        a1 += __shfl_xor_sync(0xFFFFFFFFu, a1, o);
        a2 += __shfl_xor_sync(0xFFFFFFFFu, a2, o);
        a3 += __shfl_xor_sync(0xFFFFFFFFu, a3, o);
        a4 += __shfl_xor_sync(0xFFFFFFFFu, a4, o);
        a5 += __shfl_xor_sync(0xFFFFFFFFu, a5, o);
        a6 += __shfl_xor_sync(0xFFFFFFFFu, a6, o);
        a7 += __shfl_xor_sync(0xFFFFFFFFu, a7, o);
    }

    // self + scale + bias (all lanes; lanes 0-7 canonical)
    uint4 us = h8[(size_t)node * 8 + c8];
    float2 s0 = __half22float2(*(__half2*)&us.x);
    float2 s1 = __half22float2(*(__half2*)&us.y);
    float2 s2 = __half22float2(*(__half2*)&us.z);
    float2 s3 = __half22float2(*(__half2*)&us.w);
    float dd = g_dinv[g][node];
    const float4 bv0 = *(const float4*)&b[c8 * 8];
    const float4 bv1 = *(const float4*)&b[c8 * 8 + 4];
    float z0 = fmaf(dd, a0 + s0.x, bv0.x);
    float z1 = fmaf(dd, a1 + s0.y, bv0.y);
    float z2 = fmaf(dd, a2 + s1.x, bv0.z);
    float z3 = fmaf(dd, a3 + s1.y, bv0.w);
    float z4 = fmaf(dd, a4 + s2.x, bv1.x);
    float z5 = fmaf(dd, a5 + s2.y, bv1.y);
    float z6 = fmaf(dd, a6 + s3.x, bv1.z);
    float z7 = fmaf(dd, a7 + s3.y, bv1.w);

    if (!Wy) {  // layer 1: lanes 0-7 store all 64 cols (2x float4 per lane)
        if (q == 0) {
            float* dst = &g_B[g][(size_t)node * 64 + c8 * 8];
            *(float4*)dst       = make_float4(z0, z1, z2, z3);
            *(float4*)(dst + 4) = make_float4(z4, z5, z6, z7);
        }
        return;
    }
    // layer 2: fused heads — partial dots per lane, reduce over 8-lane segment
    if (g == 0) {
        float4 wy0 = *(const float4*)&Wy[c8 * 8], wy1 = *(const float4*)&Wy[c8 * 8 + 4];
        float4 wp0 = *(const float4*)&Wp[c8 * 8], wp1 = *(const float4*)&Wp[c8 * 8 + 4];
        float4 wb0 = *(const float4*)&Wb[c8 * 8], wb1 = *(const float4*)&Wb[c8 * 8 + 4];
        float sy = z0*wy0.x + z1*wy0.y + z2*wy0.z + z3*wy0.w + z4*wy1.x + z5*wy1.y + z6*wy1.z + z7*wy1.w;
        float sp = z0*wp0.x + z1*wp0.y + z2*wp0.z + z3*wp0.w + z4*wp1.x + z5*wp1.y + z6*wp1.z + z7*wp1.w;
        float sb = z0*wb0.x + z1*wb0.y + z2*wb0.z + z3*wb0.w + z4*wb1.x + z5*wb1.y + z6*wb1.z + z7*wb1.w;
#pragma unroll
        for (int o = 4; o; o >>= 1) {
            sy += __shfl_down_sync(0xFFFFFFFFu, sy, o, 8);
            sp += __shfl_down_sync(0xFFFFFFFFu, sp, o, 8);
            sb += __shfl_down_sync(0xFFFFFFFFu, sb, o, 8);
        }
        if (lane == 0) {
            out[node]                 = fmaxf(sy + by[0], 0.f);  // yi
            out[(size_t)n + node]     = fmaxf(sp + bp[0], 0.f);  // fprob
            out[(size_t)3 * n + node] = fmaxf(sb + bb[0], 0.f);  // treat_prob
        }
    } else {
        float4 wp0 = *(const float4*)&Wp[c8 * 8], wp1 = *(const float4*)&Wp[c8 * 8 + 4];
        float sf = z0*wp0.x + z1*wp0.y + z2*wp0.z + z3*wp0.w + z4*wp1.x + z5*wp1.y + z6*wp1.z + z7*wp1.w;
#pragma unroll
        for (int o = 4; o; o >>= 1)
            sf += __shfl_down_sync(0xFFFFFFFFu, sf, o, 8);
        if (lane == 0)
            out[(size_t)2 * n + node] = fmaxf(sf + bp[0], 0.f);  // fprob_f
    }
}

// ---------------- launch ----------------

extern "C" void kernel_launch(void* const* d_in, const int* in_sizes, int n_in,
                              void* d_out, int out_size) {
    const float* x   = (const float*)d_in[0];
    const int*   ei  = (const int*)d_in[1];    // int32 on the wire
    const float* fx  = (const float*)d_in[2];
    const int*   fei = (const int*)d_in[3];
    const float* W1 = (const float*)d_in[4];
    const float* b1 = (const float*)d_in[5];
    const float* W2 = (const float*)d_in[6];
    const float* b2 = (const float*)d_in[7];
    const float* Wy = (const float*)d_in[8];
    const float* by = (const float*)d_in[9];
    const float* Wp = (const float*)d_in[10];
    const float* bp = (const float*)d_in[11];
    const float* Wb = (const float*)d_in[12];
    const float* bb = (const float*)d_in[13];

    int n = in_sizes[0] / 64;
    int E = in_sizes[1] / 2;
    float* out = (float*)d_out;

    dim3 ge4((E + 1023) / 1024, 2);
    dim3 gs((n + 1023) / 1024, 2);
    dim3 g3((n + 255) / 256, 2);
    dim3 gg((n + 63) / 64, 2);
    dim3 gw((n * 32 + 255) / 256, 2);

    // CSR build (deg starts zero: module init / scan3 reset)
    hist_kernel<<<ge4, 256>>>(ei, fei, E, n);      // rank claim
    scan1_kernel<<<gs, 1024>>>(n);                 // deg scan + dinv
    scan3_kernel<<<g3, 256>>>(n, E);               // rowptr + deg reset
    claim_kernel<<<ge4, 256>>>(ei, fei, E, n);     // atomic-free CSR scatter

    // layer 1
    gemm64_kernel<<<gg, 256>>>(x, fx, 0, W1, n, 0);
    agg_kernel<<<gw, 256>>>(b1, n, nullptr, nullptr, nullptr, nullptr, nullptr, nullptr, nullptr);

    // layer 2 (+ fused heads)
    gemm64_kernel<<<gg, 256>>>(nullptr, nullptr, 1, W2, n, 1);
    agg_kernel<<<gw, 256>>>(b2, n, Wy, by, Wp, bp, Wb, bb, out);
}

// round 13
// speedup vs baseline: 1.1430x; 1.1430x over previous
#include <cuda_runtime.h>
#include <cuda_fp16.h>
#include <cstdint>

#define N_CAP 100000
#define E_CAP 1600000

// ---------------- scratch (__device__ globals, zero-initialized) ----------------
__device__ float  g_dinv[2][N_CAP];
__device__ int    g_deg[2][N_CAP];        // zero at entry; scan3 re-zeroes
__device__ int    g_incl[2][N_CAP];
__device__ int    g_rowptr[2][N_CAP + 1];
__device__ int    g_bsum[2][128];
__device__ int    g_rank[2][E_CAP];       // per-edge rank within its dst row
__device__ int    g_esrc[2][E_CAP];       // dst-sorted src ids
__device__ __half g_A[2][(size_t)N_CAP * 64];   // h' = dinv * (X @ W), fp16
__device__ float  g_B[2][(size_t)N_CAP * 64];   // Z1 (fp32)

static __device__ __forceinline__ int clampi(int v, int lo, int hi) {
    return v < lo ? lo : (v > hi ? hi : v);
}

// ---------------- hist: per-edge rank claim (4 edges/thread, atomic MLP) ---------

__global__ void hist_kernel(const int* __restrict__ e0, const int* __restrict__ e1,
                            int E, int n) {
    int g = blockIdx.y;
    const int* dst = (g == 0 ? e0 : e1) + E;
    int base_e = blockIdx.x * 1024 + threadIdx.x;
#pragma unroll
    for (int k = 0; k < 4; k++) {
        int e = base_e + k * 256;
        if (e < E) {
            int d = clampi(dst[e], 0, n - 1);
            g_rank[g][e] = atomicAdd(&g_deg[g][d], 1);
        }
    }
}

// ---------------- scan1: per-1024-chunk inclusive scan + dinv ----------------

__global__ void scan1_kernel(int n) {
    __shared__ int sh[1024];
    int g = blockIdx.y;
    int i = blockIdx.x * 1024 + threadIdx.x;
    int v = (i < n) ? g_deg[g][i] : 0;
    if (i < n) g_dinv[g][i] = rsqrtf((float)v + 1.0f);  // self-loop
    sh[threadIdx.x] = v;
    __syncthreads();
#pragma unroll
    for (int off = 1; off < 1024; off <<= 1) {
        int t = (threadIdx.x >= off) ? sh[threadIdx.x - off] : 0;
        __syncthreads();
        sh[threadIdx.x] += t;
        __syncthreads();
    }
    if (i < n) g_incl[g][i] = sh[threadIdx.x];
    if (threadIdx.x == 1023) g_bsum[g][blockIdx.x] = sh[1023];
}

// ---------------- scan3: rowptr finalize + deg reset ----------------

__global__ void scan3_kernel(int n, int E) {
    __shared__ int sh_off;
    int g = blockIdx.y;
    int t = threadIdx.x;
    int chunk = (blockIdx.x * 256) >> 10;
    if (t < 32) {
        int s = 0;
        for (int k = t; k < chunk; k += 32) s += g_bsum[g][k];
#pragma unroll
        for (int o = 16; o; o >>= 1) s += __shfl_down_sync(0xFFFFFFFFu, s, o);
        if (t == 0) sh_off = s;
    }
    __syncthreads();
    int off = sh_off;
    int i = blockIdx.x * 256 + t;
    if (i < n) {
        g_rowptr[g][i] = g_incl[g][i] - g_deg[g][i] + off;  // exclusive
        g_deg[g][i] = 0;                                     // reset invariant
    }
    if (i == 0) g_rowptr[g][n] = E;
}

// ---------------- claim: atomic-free CSR scatter (4 edges/thread MLP) ------------

__global__ void claim_kernel(const int* __restrict__ e0, const int* __restrict__ e1,
                             int E, int n) {
    int g = blockIdx.y;
    const int* base = (g == 0 ? e0 : e1);
    int base_e = blockIdx.x * 1024 + threadIdx.x;
#pragma unroll
    for (int k = 0; k < 4; k++) {
        int e = base_e + k * 256;
        if (e < E) {
            int s = clampi(base[e], 0, n - 1);
            int d = clampi(base[E + e], 0, n - 1);
            int pos = g_rowptr[g][d] + g_rank[g][e];
            g_esrc[g][pos] = s;
        }
    }
}

// ---------------- GEMM: h' = dinv * ((relu?)X @ W), fp16 out (R9 version) --------

__global__ void gemm64_kernel(const float* __restrict__ X0, const float* __restrict__ X1,
                              int use_B, const float* __restrict__ W, int n, int relu_in) {
    __shared__ float Ws[64][64];
    __shared__ float Xs[64][65];
    int g = blockIdx.y;
    const float* X = use_B ? (const float*)g_B[g] : (g == 0 ? X0 : X1);
    __half* Y = g_A[g];
    int tid = threadIdx.x;
    for (int i = tid; i < 64 * 16; i += 256)
        ((float4*)Ws)[i] = ((const float4*)W)[i];
    int row0 = blockIdx.x * 64;
    for (int i = tid; i < 64 * 16; i += 256) {
        int r = i >> 4, c = (i & 15) * 4;
        float4 v = make_float4(0.f, 0.f, 0.f, 0.f);
        if (row0 + r < n) v = *(const float4*)&X[(size_t)(row0 + r) * 64 + c];
        if (relu_in) {
            v.x = fmaxf(v.x, 0.f); v.y = fmaxf(v.y, 0.f);
            v.z = fmaxf(v.z, 0.f); v.w = fmaxf(v.w, 0.f);
        }
        Xs[r][c] = v.x; Xs[r][c + 1] = v.y; Xs[r][c + 2] = v.z; Xs[r][c + 3] = v.w;
    }
    __syncthreads();
    int tr = (tid >> 4) * 4;
    int tc = tid & 15;
    float acc[4][4] = {};
#pragma unroll
    for (int k = 0; k < 64; k++) {
        float4 w4 = ((const float4*)&Ws[k][0])[tc];
        float x0 = Xs[tr + 0][k], x1 = Xs[tr + 1][k];
        float x2 = Xs[tr + 2][k], x3 = Xs[tr + 3][k];
        acc[0][0] += x0 * w4.x; acc[0][1] += x0 * w4.y; acc[0][2] += x0 * w4.z; acc[0][3] += x0 * w4.w;
        acc[1][0] += x1 * w4.x; acc[1][1] += x1 * w4.y; acc[1][2] += x1 * w4.z; acc[1][3] += x1 * w4.w;
        acc[2][0] += x2 * w4.x; acc[2][1] += x2 * w4.y; acc[2][2] += x2 * w4.z; acc[2][3] += x2 * w4.w;
        acc[3][0] += x3 * w4.x; acc[3][1] += x3 * w4.y; acc[3][2] += x3 * w4.z; acc[3][3] += x3 * w4.w;
    }
#pragma unroll
    for (int i = 0; i < 4; i++) {
        int r = row0 + tr + i;
        if (r < n) {
            float dv = g_dinv[g][r];
            __half2 p0 = __floats2half2_rn(acc[i][0] * dv, acc[i][1] * dv);
            __half2 p1 = __floats2half2_rn(acc[i][2] * dv, acc[i][3] * dv);
            uint2 u = make_uint2(*(unsigned*)&p0, *(unsigned*)&p1);
            *(uint2*)&Y[(size_t)r * 64 + tc * 4] = u;
        }
    }
}

// ---------------- aggregation: Z = dinv[d]*(Σ h'[src] + h'[d]) + b ----------------
// R9 version: warp per node; lanes split 16/16, each load covers TWO edge rows.

__global__ void agg_kernel(const float* __restrict__ b, int n,
                           const float* __restrict__ Wy, const float* __restrict__ by,
                           const float* __restrict__ Wp, const float* __restrict__ bp,
                           const float* __restrict__ Wb, const float* __restrict__ bb,
                           float* __restrict__ out) {
    int g = blockIdx.y;
    int node = (blockIdx.x * blockDim.x + threadIdx.x) >> 5;
    int lane = threadIdx.x & 31;
    if (node >= n) return;
    const uint2* __restrict__ h4 = (const uint2*)g_A[g];
    const int*   __restrict__ ep = g_esrc[g];

    int half = lane >> 4;
    int c4   = lane & 15;
    float a0 = 0.f, a1 = 0.f, a2 = 0.f, a3 = 0.f;

    int beg = g_rowptr[g][node];
    int end = g_rowptr[g][node + 1];

    for (int jj = beg; jj < end; jj += 8) {
#pragma unroll
        for (int s = 0; s < 4; s++) {
            int my = jj + s * 2 + half;
            if (my < end) {
                int src = ep[my];
                uint2 u = h4[(size_t)src * 16 + c4];
                float2 f0 = __half22float2(*(__half2*)&u.x);
                float2 f1 = __half22float2(*(__half2*)&u.y);
                a0 += f0.x; a1 += f0.y; a2 += f1.x; a3 += f1.y;
            }
        }
    }
    a0 += __shfl_xor_sync(0xFFFFFFFFu, a0, 16);
    a1 += __shfl_xor_sync(0xFFFFFFFFu, a1, 16);
    a2 += __shfl_xor_sync(0xFFFFFFFFu, a2, 16);
    a3 += __shfl_xor_sync(0xFFFFFFFFu, a3, 16);

    uint2 us = h4[(size_t)node * 16 + c4];
    float2 s0 = __half22float2(*(__half2*)&us.x);
    float2 s1 = __half22float2(*(__half2*)&us.y);
    float dd = g_dinv[g][node];
    const float4 bv = *(const float4*)&b[c4 * 4];
    float z0 = fmaf(dd, a0 + s0.x, bv.x);
    float z1 = fmaf(dd, a1 + s0.y, bv.y);
    float z2 = fmaf(dd, a2 + s1.x, bv.z);
    float z3 = fmaf(dd, a3 + s1.y, bv.w);

    if (!Wy) {  // layer 1
        if (half == 0)
            *(float4*)&g_B[g][(size_t)node * 64 + c4 * 4] = make_float4(z0, z1, z2, z3);
        return;
    }
    if (g == 0) {
        float4 wy = *(const float4*)&Wy[c4 * 4];
        float4 wp = *(const float4*)&Wp[c4 * 4];
        float4 wb = *(const float4*)&Wb[c4 * 4];
        float sy = z0 * wy.x + z1 * wy.y + z2 * wy.z + z3 * wy.w;
        float sp = z0 * wp.x + z1 * wp.y + z2 * wp.z + z3 * wp.w;
        float sb = z0 * wb.x + z1 * wb.y + z2 * wb.z + z3 * wb.w;
#pragma unroll
        for (int o = 8; o; o >>= 1) {
            sy += __shfl_down_sync(0xFFFFFFFFu, sy, o, 16);
            sp += __shfl_down_sync(0xFFFFFFFFu, sp, o, 16);
            sb += __shfl_down_sync(0xFFFFFFFFu, sb, o, 16);
        }
        if (lane == 0) {
            out[node]                 = fmaxf(sy + by[0], 0.f);  // yi
            out[(size_t)n + node]     = fmaxf(sp + bp[0], 0.f);  // fprob
            out[(size_t)3 * n + node] = fmaxf(sb + bb[0], 0.f);  // treat_prob
        }
    } else {
        float4 wp = *(const float4*)&Wp[c4 * 4];
        float sf = z0 * wp.x + z1 * wp.y + z2 * wp.z + z3 * wp.w;
#pragma unroll
        for (int o = 8; o; o >>= 1)
            sf += __shfl_down_sync(0xFFFFFFFFu, sf, o, 16);
        if (lane == 0)
            out[(size_t)2 * n + node] = fmaxf(sf + bp[0], 0.f);  // fprob_f
    }
}

// ---------------- launch ----------------

extern "C" void kernel_launch(void* const* d_in, const int* in_sizes, int n_in,
                              void* d_out, int out_size) {
    const float* x   = (const float*)d_in[0];
    const int*   ei  = (const int*)d_in[1];    // int32 on the wire
    const float* fx  = (const float*)d_in[2];
    const int*   fei = (const int*)d_in[3];
    const float* W1 = (const float*)d_in[4];
    const float* b1 = (const float*)d_in[5];
    const float* W2 = (const float*)d_in[6];
    const float* b2 = (const float*)d_in[7];
    const float* Wy = (const float*)d_in[8];
    const float* by = (const float*)d_in[9];
    const float* Wp = (const float*)d_in[10];
    const float* bp = (const float*)d_in[11];
    const float* Wb = (const float*)d_in[12];
    const float* bb = (const float*)d_in[13];

    int n = in_sizes[0] / 64;
    int E = in_sizes[1] / 2;
    float* out = (float*)d_out;

    // side stream + fork/join events (created on uncaptured correctness call,
    // reused during capture — capture-legal).
    static cudaStream_t s2 = nullptr;
    static cudaEvent_t ev_fork = nullptr, ev_join = nullptr;
    if (!s2) {
        cudaStreamCreateWithFlags(&s2, cudaStreamNonBlocking);
        cudaEventCreateWithFlags(&ev_fork, cudaEventDisableTiming);
        cudaEventCreateWithFlags(&ev_join, cudaEventDisableTiming);
    }

    dim3 ge4((E + 1023) / 1024, 2);
    dim3 gs((n + 1023) / 1024, 2);
    dim3 g3((n + 255) / 256, 2);
    dim3 gg((n + 63) / 64, 2);
    dim3 gw((n * 32 + 255) / 256, 2);

    // CSR build head
    hist_kernel<<<ge4, 256>>>(ei, fei, E, n);      // rank claim
    scan1_kernel<<<gs, 1024>>>(n);                 // deg scan + dinv

    // fork: gemm1 (needs only dinv) overlaps scan3 + claim in the graph DAG
    cudaEventRecord(ev_fork, 0);
    cudaStreamWaitEvent(s2, ev_fork, 0);
    gemm64_kernel<<<gg, 256, 0, s2>>>(x, fx, 0, W1, n, 0);
    cudaEventRecord(ev_join, s2);

    scan3_kernel<<<g3, 256>>>(n, E);               // rowptr + deg reset
    claim_kernel<<<ge4, 256>>>(ei, fei, E, n);     // atomic-free CSR scatter

    cudaStreamWaitEvent(0, ev_join, 0);
    agg_kernel<<<gw, 256>>>(b1, n, nullptr, nullptr, nullptr, nullptr, nullptr, nullptr, nullptr);

    // layer 2 (+ fused heads)
    gemm64_kernel<<<gg, 256>>>(nullptr, nullptr, 1, W2, n, 1);
    agg_kernel<<<gw, 256>>>(b2, n, Wy, by, Wp, bp, Wb, bb, out);
}